// round 6
// baseline (speedup 1.0000x reference)
#include <cuda_runtime.h>

#define D      512
#define W      5
#define TPB    128
#define DV4    (D / 4)
#define MAX_TIME_ROWS 512

// Precomputed (sin, cos) pairs of the time table, interleaved: g_trig[row*D + d] = (s, c).
__device__ float2 g_trig[MAX_TIME_ROWS * D];

__global__ void trig_kernel(const float* __restrict__ tt, int n) {
    int i = blockIdx.x * blockDim.x + threadIdx.x;
    if (i < n) {
        float s, c;
        sincosf(tt[i], &s, &c);
        g_trig[i] = make_float2(s, c);
    }
}

__global__ __launch_bounds__(TPB, 8) void contxe_kernel(
    const int*   __restrict__ h_i,
    const int*   __restrict__ t_i,
    const int*   __restrict__ r_i,
    const int*   __restrict__ d_i,
    const float* __restrict__ eEr,
    const float* __restrict__ eEi,
    const float* __restrict__ eRr,
    const float* __restrict__ eRi,
    float*       __restrict__ out,
    int n_day)
{
    const int b    = blockIdx.x;
    const int tid  = threadIdx.x;
    const int lane = tid & 31;
    const int warp = tid >> 5;

    // Trig staged as (s,c) pairs: float4 = 2 pairs. [W][D/2] float4 = 20 KB.
    __shared__ float4 sh_trig[W * (D / 2)];
    __shared__ float  sh_red[32 * 20];   // 2.5 KB: 32 writer-groups x 20 partials
    __shared__ float  sh_w[20];
    __shared__ float  partial[4];

    const int h = h_i[b];
    const int t = t_i[b];
    const int r = r_i[b];
    const int d = d_i[b];

    // ---- Stage trig rows for this window into smem (L2 hits) ----
    const float4* gt = (const float4*)g_trig;   // 2 (s,c) pairs per float4
    #pragma unroll
    for (int w = 0; w < W; w++) {
        int row = d - (W - 1 - w);
        if (row < 0) row = n_day;
        // pairs 2*tid and 2*tid+1 cover d = 4*tid .. 4*tid+3
        sh_trig[w * (D / 2) + 2 * tid]     = gt[row * (D / 2) + 2 * tid];
        sh_trig[w * (D / 2) + 2 * tid + 1] = gt[row * (D / 2) + 2 * tid + 1];
    }

    // ---- Embedding gathers (coalesced full rows, front-batched for MLP) ----
    const float4 hr4 = ((const float4*)(eEr + (size_t)h * D))[tid];
    const float4 hi4 = ((const float4*)(eEi + (size_t)h * D))[tid];
    const float4 tr4 = ((const float4*)(eEr + (size_t)t * D))[tid];
    const float4 ti4 = ((const float4*)(eEi + (size_t)t * D))[tid];
    const float4 rr4 = ((const float4*)(eRr + (size_t)r * D))[tid];
    const float4 ri4 = ((const float4*)(eRi + (size_t)r * D))[tid];

    const float* hrp = (const float*)&hr4;
    const float* hip = (const float*)&hi4;
    const float* trp = (const float*)&tr4;
    const float* tip = (const float*)&ti4;
    const float* rrp = (const float*)&rr4;
    const float* rip = (const float*)&ri4;

    __syncthreads();

    // ---- Pass 1: 20 attention-score partial dots (rotation form) ----
    float acc[20];
    #pragma unroll
    for (int j = 0; j < 20; j++) acc[j] = 0.0f;

    #pragma unroll
    for (int w = 0; w < W; w++) {
        const float4 t0 = sh_trig[w * (D / 2) + 2 * tid];
        const float4 t1 = sh_trig[w * (D / 2) + 2 * tid + 1];
        const float sv[4] = { t0.x, t0.z, t1.x, t1.z };
        const float cv[4] = { t0.y, t0.w, t1.y, t1.w };
        #pragma unroll
        for (int k = 0; k < 4; k++) {
            const float s = sv[k], c = cv[k];
            const float hre = fmaf(hrp[k], c, -hip[k] * s);
            const float him = fmaf(hrp[k], s,  hip[k] * c);
            const float tre = fmaf(trp[k], c, -tip[k] * s);
            const float tim = fmaf(trp[k], s,  tip[k] * c);
            acc[0 * W + w] = fmaf(rrp[k], hre, acc[0 * W + w]);
            acc[1 * W + w] = fmaf(rip[k], him, acc[1 * W + w]);
            acc[2 * W + w] = fmaf(rrp[k], tre, acc[2 * W + w]);
            acc[3 * W + w] = fmaf(rip[k], tim, acc[3 * W + w]);
        }
    }

    // ---- Pre-reduce across groups of 4 lanes (2 shuffle rounds), then dump ----
    #pragma unroll
    for (int j = 0; j < 20; j++) {
        acc[j] += __shfl_xor_sync(0xffffffffu, acc[j], 1);
        acc[j] += __shfl_xor_sync(0xffffffffu, acc[j], 2);
    }
    if ((tid & 3) == 0) {
        float4* rp = (float4*)(sh_red + (tid >> 2) * 20);
        #pragma unroll
        for (int j = 0; j < 5; j++)
            rp[j] = make_float4(acc[4 * j], acc[4 * j + 1], acc[4 * j + 2], acc[4 * j + 3]);
    }
    __syncthreads();

    // ---- Warp 0: column sums (32 rows) + 4 softmaxes, all intra-warp ----
    if (warp == 0) {
        const int j = (lane < 20) ? lane : 0;
        float v0 = 0.f, v1 = 0.f, v2 = 0.f, v3 = 0.f;
        #pragma unroll
        for (int i = 0; i < 32; i += 4) {
            v0 += sh_red[(i + 0) * 20 + j];
            v1 += sh_red[(i + 1) * 20 + j];
            v2 += sh_red[(i + 2) * 20 + j];
            v3 += sh_red[(i + 3) * 20 + j];
        }
        float sc = (v0 + v1) + (v2 + v3);

        const int base = (j / 5) * 5;
        const int pos  = j - base;
        float m = sc;
        #pragma unroll
        for (int off = 1; off < W; off++)
            m = fmaxf(m, __shfl_sync(0xffffffffu, sc, base + (pos + off) % W));
        const float e = expf(sc - m);
        float tot = e;
        #pragma unroll
        for (int off = 1; off < W; off++)
            tot += __shfl_sync(0xffffffffu, e, base + (pos + off) % W);
        if (lane < 20) sh_w[lane] = e / tot;
    }
    __syncthreads();

    // ---- Pass 2: weighted sums (rotation form) + L1 score ----
    float yre[4] = {0, 0, 0, 0};
    float yim[4] = {0, 0, 0, 0};
    float zre[4] = {0, 0, 0, 0};
    float zim[4] = {0, 0, 0, 0};

    #pragma unroll
    for (int w = 0; w < W; w++) {
        const float wa_r = sh_w[0 * W + w];   // LDS broadcasts
        const float wa_i = sh_w[1 * W + w];
        const float wb_r = sh_w[2 * W + w];
        const float wb_i = sh_w[3 * W + w];
        const float4 t0 = sh_trig[w * (D / 2) + 2 * tid];
        const float4 t1 = sh_trig[w * (D / 2) + 2 * tid + 1];
        const float sv[4] = { t0.x, t0.z, t1.x, t1.z };
        const float cv[4] = { t0.y, t0.w, t1.y, t1.w };
        #pragma unroll
        for (int k = 0; k < 4; k++) {
            const float s = sv[k], c = cv[k];
            const float hre = fmaf(hrp[k], c, -hip[k] * s);
            const float him = fmaf(hrp[k], s,  hip[k] * c);
            const float tre = fmaf(trp[k], c, -tip[k] * s);
            const float tim = fmaf(trp[k], s,  tip[k] * c);
            yre[k] = fmaf(wa_r, hre, yre[k]);
            yim[k] = fmaf(wa_i, him, yim[k]);
            zre[k] = fmaf(wb_r, tre, zre[k]);
            zim[k] = fmaf(wb_i, tim, zim[k]);
        }
    }

    float local = 0.0f;
    #pragma unroll
    for (int k = 0; k < 4; k++) {
        local += fabsf(yre[k] + rrp[k] - zre[k]);
        local += fabsf(yim[k] + rip[k] + zim[k]);
    }

    local += __shfl_xor_sync(0xffffffffu, local, 16);
    local += __shfl_xor_sync(0xffffffffu, local, 8);
    local += __shfl_xor_sync(0xffffffffu, local, 4);
    local += __shfl_xor_sync(0xffffffffu, local, 2);
    local += __shfl_xor_sync(0xffffffffu, local, 1);
    if (lane == 0) partial[warp] = local;
    __syncthreads();

    if (tid == 0) {
        out[b] = (partial[0] + partial[1]) + (partial[2] + partial[3]);
    }
}

extern "C" void kernel_launch(void* const* d_in, const int* in_sizes, int n_in,
                              void* d_out, int out_size) {
    const int*   h_i = (const int*)  d_in[0];
    const int*   t_i = (const int*)  d_in[1];
    const int*   r_i = (const int*)  d_in[2];
    const int*   d_i = (const int*)  d_in[3];
    const float* eEr = (const float*)d_in[4];
    const float* eEi = (const float*)d_in[5];
    const float* eRr = (const float*)d_in[6];
    const float* eRi = (const float*)d_in[7];
    const float* tt  = (const float*)d_in[8];

    const int B          = in_sizes[0];
    const int time_elems = in_sizes[8];
    const int time_rows  = time_elems / D;
    const int n_day      = time_rows - 2;

    trig_kernel<<<(time_elems + 255) / 256, 256>>>(tt, time_elems);
    contxe_kernel<<<B, TPB>>>(h_i, t_i, r_i, d_i, eEr, eEi, eRr, eRi,
                              (float*)d_out, n_day);
}

// round 8
// speedup vs baseline: 1.1727x; 1.1727x over previous
#include <cuda_runtime.h>
#include <cuda_fp16.h>

#define D      512
#define W      5
#define TPB    128
#define MAX_TIME_ROWS 512

// Precomputed (sin, cos) of the time table as fp16 pairs: g_trig[row*D + d] = half2(s, c).
// 367*512*4B = 750 KB — fully L2-resident.
__device__ __half2 g_trig[MAX_TIME_ROWS * D];

__global__ void trig_kernel(const float* __restrict__ tt, int n) {
    int i = blockIdx.x * blockDim.x + threadIdx.x;
    if (i < n) {
        float s, c;
        sincosf(tt[i], &s, &c);
        g_trig[i] = __floats2half2_rn(s, c);
    }
}

__global__ __launch_bounds__(TPB, 6) void contxe_kernel(
    const int*   __restrict__ h_i,
    const int*   __restrict__ t_i,
    const int*   __restrict__ r_i,
    const int*   __restrict__ d_i,
    const float* __restrict__ eEr,
    const float* __restrict__ eEi,
    const float* __restrict__ eRr,
    const float* __restrict__ eRi,
    float*       __restrict__ out,
    int n_day)
{
    const int b    = blockIdx.x;
    const int tid  = threadIdx.x;
    const int lane = tid & 31;
    const int warp = tid >> 5;

    __shared__ float sh_red[32 * 20];   // 2.5 KB
    __shared__ float sh_w[20];
    __shared__ float partial[4];

    const int h = h_i[b];
    const int t = t_i[b];
    const int r = r_i[b];
    const int d = d_i[b];

    // ---- Trig: one LDG.128 per window slot = 4 (s,c) fp16 pairs (elems 4*tid..4*tid+3) ----
    uint4 T[W];
    const uint4* gt = (const uint4*)g_trig;   // 4 half2 per uint4; D/4 = 128 uint4 per row
    #pragma unroll
    for (int w = 0; w < W; w++) {
        int row = d - (W - 1 - w);
        if (row < 0) row = n_day;
        T[w] = gt[row * (D / 4) + tid];
    }

    // ---- Embedding gathers (coalesced full rows, front-batched for MLP) ----
    const float4 hr4 = ((const float4*)(eEr + (size_t)h * D))[tid];
    const float4 hi4 = ((const float4*)(eEi + (size_t)h * D))[tid];
    const float4 tr4 = ((const float4*)(eEr + (size_t)t * D))[tid];
    const float4 ti4 = ((const float4*)(eEi + (size_t)t * D))[tid];
    const float4 rr4 = ((const float4*)(eRr + (size_t)r * D))[tid];
    const float4 ri4 = ((const float4*)(eRi + (size_t)r * D))[tid];

    const float* hrp = (const float*)&hr4;
    const float* hip = (const float*)&hi4;
    const float* trp = (const float*)&tr4;
    const float* tip = (const float*)&ti4;
    const float* rrp = (const float*)&rr4;
    const float* rip = (const float*)&ri4;

    // ---- Pass 1: 20 attention-score partial dots (rotation form) ----
    float acc[20];
    #pragma unroll
    for (int j = 0; j < 20; j++) acc[j] = 0.0f;

    #pragma unroll
    for (int w = 0; w < W; w++) {
        const __half2* tp = (const __half2*)&T[w];
        #pragma unroll
        for (int k = 0; k < 4; k++) {
            const float2 sc = __half22float2(tp[k]);
            const float s = sc.x, c = sc.y;
            const float hre = fmaf(hrp[k], c, -hip[k] * s);
            const float him = fmaf(hrp[k], s,  hip[k] * c);
            const float tre = fmaf(trp[k], c, -tip[k] * s);
            const float tim = fmaf(trp[k], s,  tip[k] * c);
            acc[0 * W + w] = fmaf(rrp[k], hre, acc[0 * W + w]);
            acc[1 * W + w] = fmaf(rip[k], him, acc[1 * W + w]);
            acc[2 * W + w] = fmaf(rrp[k], tre, acc[2 * W + w]);
            acc[3 * W + w] = fmaf(rip[k], tim, acc[3 * W + w]);
        }
    }

    // ---- Pre-reduce across groups of 4 lanes (2 shuffle rounds), then dump ----
    #pragma unroll
    for (int j = 0; j < 20; j++) {
        acc[j] += __shfl_xor_sync(0xffffffffu, acc[j], 1);
        acc[j] += __shfl_xor_sync(0xffffffffu, acc[j], 2);
    }
    if ((tid & 3) == 0) {
        float4* rp = (float4*)(sh_red + (tid >> 2) * 20);
        #pragma unroll
        for (int j = 0; j < 5; j++)
            rp[j] = make_float4(acc[4 * j], acc[4 * j + 1], acc[4 * j + 2], acc[4 * j + 3]);
    }
    __syncthreads();

    // ---- Warp 0: column sums (32 rows) + 4 softmaxes, all intra-warp ----
    if (warp == 0) {
        const int j = (lane < 20) ? lane : 0;
        float v0 = 0.f, v1 = 0.f, v2 = 0.f, v3 = 0.f;
        #pragma unroll
        for (int i = 0; i < 32; i += 4) {
            v0 += sh_red[(i + 0) * 20 + j];
            v1 += sh_red[(i + 1) * 20 + j];
            v2 += sh_red[(i + 2) * 20 + j];
            v3 += sh_red[(i + 3) * 20 + j];
        }
        float sc = (v0 + v1) + (v2 + v3);

        const int base = (j / 5) * 5;
        const int pos  = j - base;
        float m = sc;
        #pragma unroll
        for (int off = 1; off < W; off++)
            m = fmaxf(m, __shfl_sync(0xffffffffu, sc, base + (pos + off) % W));
        const float e = expf(sc - m);
        float tot = e;
        #pragma unroll
        for (int off = 1; off < W; off++)
            tot += __shfl_sync(0xffffffffu, e, base + (pos + off) % W);
        if (lane < 20) sh_w[lane] = e / tot;
    }
    __syncthreads();

    // ---- Pass 2: weighted sums (rotation form, trig reused from registers) ----
    float yre[4] = {0, 0, 0, 0};
    float yim[4] = {0, 0, 0, 0};
    float zre[4] = {0, 0, 0, 0};
    float zim[4] = {0, 0, 0, 0};

    #pragma unroll
    for (int w = 0; w < W; w++) {
        const float wa_r = sh_w[0 * W + w];   // LDS broadcasts
        const float wa_i = sh_w[1 * W + w];
        const float wb_r = sh_w[2 * W + w];
        const float wb_i = sh_w[3 * W + w];
        const __half2* tp = (const __half2*)&T[w];
        #pragma unroll
        for (int k = 0; k < 4; k++) {
            const float2 sc = __half22float2(tp[k]);
            const float s = sc.x, c = sc.y;
            const float hre = fmaf(hrp[k], c, -hip[k] * s);
            const float him = fmaf(hrp[k], s,  hip[k] * c);
            const float tre = fmaf(trp[k], c, -tip[k] * s);
            const float tim = fmaf(trp[k], s,  tip[k] * c);
            yre[k] = fmaf(wa_r, hre, yre[k]);
            yim[k] = fmaf(wa_i, him, yim[k]);
            zre[k] = fmaf(wb_r, tre, zre[k]);
            zim[k] = fmaf(wb_i, tim, zim[k]);
        }
    }

    float local = 0.0f;
    #pragma unroll
    for (int k = 0; k < 4; k++) {
        local += fabsf(yre[k] + rrp[k] - zre[k]);
        local += fabsf(yim[k] + rip[k] + zim[k]);
    }

    local += __shfl_xor_sync(0xffffffffu, local, 16);
    local += __shfl_xor_sync(0xffffffffu, local, 8);
    local += __shfl_xor_sync(0xffffffffu, local, 4);
    local += __shfl_xor_sync(0xffffffffu, local, 2);
    local += __shfl_xor_sync(0xffffffffu, local, 1);
    if (lane == 0) partial[warp] = local;
    __syncthreads();

    if (tid == 0) {
        out[b] = (partial[0] + partial[1]) + (partial[2] + partial[3]);
    }
}

extern "C" void kernel_launch(void* const* d_in, const int* in_sizes, int n_in,
                              void* d_out, int out_size) {
    const int*   h_i = (const int*)  d_in[0];
    const int*   t_i = (const int*)  d_in[1];
    const int*   r_i = (const int*)  d_in[2];
    const int*   d_i = (const int*)  d_in[3];
    const float* eEr = (const float*)d_in[4];
    const float* eEi = (const float*)d_in[5];
    const float* eRr = (const float*)d_in[6];
    const float* eRi = (const float*)d_in[7];
    const float* tt  = (const float*)d_in[8];

    const int B          = in_sizes[0];
    const int time_elems = in_sizes[8];
    const int time_rows  = time_elems / D;
    const int n_day      = time_rows - 2;

    trig_kernel<<<(time_elems + 255) / 256, 256>>>(tt, time_elems);
    contxe_kernel<<<B, TPB>>>(h_i, t_i, r_i, d_i, eEr, eEi, eRr, eRi,
                              (float*)d_out, n_day);
}

// round 11
// speedup vs baseline: 1.3439x; 1.1460x over previous
#include <cuda_runtime.h>
#include <cuda_fp16.h>

#define D      512
#define W      5
#define TPB    128
#define MAX_TIME_ROWS 512

// Precomputed (sin, cos) of the time table as fp16 pairs: g_trig[row*D + d] = half2(s, c).
// 367*512*4B = 750 KB — fully L2-resident.
__device__ __half2 g_trig[MAX_TIME_ROWS * D];

__global__ void trig_kernel(const float* __restrict__ tt, int n) {
    int i = blockIdx.x * blockDim.x + threadIdx.x;
    if (i < n) {
        float s, c;
        sincosf(tt[i], &s, &c);
        g_trig[i] = __floats2half2_rn(s, c);
    }
}

__global__ __launch_bounds__(TPB) void contxe_kernel(
    const int*   __restrict__ h_i,
    const int*   __restrict__ t_i,
    const int*   __restrict__ r_i,
    const int*   __restrict__ d_i,
    const float* __restrict__ eEr,
    const float* __restrict__ eEi,
    const float* __restrict__ eRr,
    const float* __restrict__ eRi,
    float*       __restrict__ out,
    int n_day)
{
    const int b    = blockIdx.x;
    const int tid  = threadIdx.x;
    const int lane = tid & 31;
    const int warp = tid >> 5;

    __shared__ float red[4][20];
    __shared__ float sh_w[20];
    __shared__ float partial[4];

    const int h = h_i[b];
    const int t = t_i[b];
    const int r = r_i[b];
    const int d = d_i[b];

    // ---- Embedding gathers FIRST (DRAM latency — get them in flight early) ----
    const float4 hr4 = ((const float4*)(eEr + (size_t)h * D))[tid];
    const float4 hi4 = ((const float4*)(eEi + (size_t)h * D))[tid];
    const float4 tr4 = ((const float4*)(eEr + (size_t)t * D))[tid];
    const float4 ti4 = ((const float4*)(eEi + (size_t)t * D))[tid];
    const float4 rr4 = ((const float4*)(eRr + (size_t)r * D))[tid];
    const float4 ri4 = ((const float4*)(eRi + (size_t)r * D))[tid];

    // ---- Trig: one LDG.128 per window slot = 4 (s,c) fp16 pairs (L2 hits) ----
    uint4 T[W];
    const uint4* gt = (const uint4*)g_trig;   // 4 half2 per uint4; D/4 = 128 uint4 per row
    #pragma unroll
    for (int w = 0; w < W; w++) {
        int row = d - (W - 1 - w);
        if (row < 0) row = n_day;
        T[w] = gt[row * (D / 4) + tid];
    }

    const float* hrp = (const float*)&hr4;
    const float* hip = (const float*)&hi4;
    const float* trp = (const float*)&tr4;
    const float* tip = (const float*)&ti4;
    const float* rrp = (const float*)&rr4;
    const float* rip = (const float*)&ri4;

    // ---- Pass 1: 20 attention-score partial dots (rotation form) ----
    float acc[20];
    #pragma unroll
    for (int j = 0; j < 20; j++) acc[j] = 0.0f;

    #pragma unroll
    for (int w = 0; w < W; w++) {
        const __half2* tp = (const __half2*)&T[w];
        #pragma unroll
        for (int k = 0; k < 4; k++) {
            const float2 sc = __half22float2(tp[k]);
            const float s = sc.x, c = sc.y;
            const float hre = fmaf(hrp[k], c, -hip[k] * s);
            const float him = fmaf(hrp[k], s,  hip[k] * c);
            const float tre = fmaf(trp[k], c, -tip[k] * s);
            const float tim = fmaf(trp[k], s,  tip[k] * c);
            acc[0 * W + w] = fmaf(rrp[k], hre, acc[0 * W + w]);
            acc[1 * W + w] = fmaf(rip[k], him, acc[1 * W + w]);
            acc[2 * W + w] = fmaf(rrp[k], tre, acc[2 * W + w]);
            acc[3 * W + w] = fmaf(rip[k], tim, acc[3 * W + w]);
        }
    }

    // ---- Warp butterfly reduce each of the 20 accumulators (R4 path) ----
    #pragma unroll
    for (int j = 0; j < 20; j++) {
        float v = acc[j];
        v += __shfl_xor_sync(0xffffffffu, v, 16);
        v += __shfl_xor_sync(0xffffffffu, v, 8);
        v += __shfl_xor_sync(0xffffffffu, v, 4);
        v += __shfl_xor_sync(0xffffffffu, v, 2);
        v += __shfl_xor_sync(0xffffffffu, v, 1);
        if (lane == 0) red[warp][j] = v;
    }
    __syncthreads();

    // ---- 4 threads each do one 5-way softmax ----
    if (tid < 4) {
        float sc[W];
        float m = -1e30f;
        #pragma unroll
        for (int w = 0; w < W; w++) {
            sc[w] = red[0][tid * W + w] + red[1][tid * W + w]
                  + red[2][tid * W + w] + red[3][tid * W + w];
            m = fmaxf(m, sc[w]);
        }
        float sum = 0.0f;
        #pragma unroll
        for (int w = 0; w < W; w++) {
            sc[w] = expf(sc[w] - m);
            sum += sc[w];
        }
        float inv = 1.0f / sum;
        #pragma unroll
        for (int w = 0; w < W; w++) sh_w[tid * W + w] = sc[w] * inv;
    }
    __syncthreads();

    // ---- Pass 2: weighted sums (rotation form, trig reused from registers) ----
    float yre[4] = {0, 0, 0, 0};
    float yim[4] = {0, 0, 0, 0};
    float zre[4] = {0, 0, 0, 0};
    float zim[4] = {0, 0, 0, 0};

    #pragma unroll
    for (int w = 0; w < W; w++) {
        const float wa_r = sh_w[0 * W + w];   // LDS broadcasts
        const float wa_i = sh_w[1 * W + w];
        const float wb_r = sh_w[2 * W + w];
        const float wb_i = sh_w[3 * W + w];
        const __half2* tp = (const __half2*)&T[w];
        #pragma unroll
        for (int k = 0; k < 4; k++) {
            const float2 sc = __half22float2(tp[k]);
            const float s = sc.x, c = sc.y;
            const float hre = fmaf(hrp[k], c, -hip[k] * s);
            const float him = fmaf(hrp[k], s,  hip[k] * c);
            const float tre = fmaf(trp[k], c, -tip[k] * s);
            const float tim = fmaf(trp[k], s,  tip[k] * c);
            yre[k] = fmaf(wa_r, hre, yre[k]);
            yim[k] = fmaf(wa_i, him, yim[k]);
            zre[k] = fmaf(wb_r, tre, zre[k]);
            zim[k] = fmaf(wb_i, tim, zim[k]);
        }
    }

    float local = 0.0f;
    #pragma unroll
    for (int k = 0; k < 4; k++) {
        local += fabsf(yre[k] + rrp[k] - zre[k]);
        local += fabsf(yim[k] + rip[k] + zim[k]);
    }

    local += __shfl_xor_sync(0xffffffffu, local, 16);
    local += __shfl_xor_sync(0xffffffffu, local, 8);
    local += __shfl_xor_sync(0xffffffffu, local, 4);
    local += __shfl_xor_sync(0xffffffffu, local, 2);
    local += __shfl_xor_sync(0xffffffffu, local, 1);
    if (lane == 0) partial[warp] = local;
    __syncthreads();

    if (tid == 0) {
        out[b] = (partial[0] + partial[1]) + (partial[2] + partial[3]);
    }
}

extern "C" void kernel_launch(void* const* d_in, const int* in_sizes, int n_in,
                              void* d_out, int out_size) {
    const int*   h_i = (const int*)  d_in[0];
    const int*   t_i = (const int*)  d_in[1];
    const int*   r_i = (const int*)  d_in[2];
    const int*   d_i = (const int*)  d_in[3];
    const float* eEr = (const float*)d_in[4];
    const float* eEi = (const float*)d_in[5];
    const float* eRr = (const float*)d_in[6];
    const float* eRi = (const float*)d_in[7];
    const float* tt  = (const float*)d_in[8];

    const int B          = in_sizes[0];
    const int time_elems = in_sizes[8];
    const int time_rows  = time_elems / D;
    const int n_day      = time_rows - 2;

    trig_kernel<<<(time_elems + 255) / 256, 256>>>(tt, time_elems);
    contxe_kernel<<<B, TPB>>>(h_i, t_i, r_i, d_i, eEr, eEi, eRr, eRi,
                              (float*)d_out, n_day);
}